// round 10
// baseline (speedup 1.0000x reference)
#include <cuda_runtime.h>
#include <cuda_bf16.h>

// B=16, N_VEC=2048, N_DIM=32, N_W=4, N_HID=128, VOCAB=32000, N_CLASS=10

typedef unsigned long long u64;

__device__ __forceinline__ unsigned f2tf32(float x) {
    unsigned r;
    asm("cvt.rna.tf32.f32 %0, %1;" : "=r"(r) : "f"(x));
    return r;
}
__device__ __forceinline__ void mma_tf32(float* c, const unsigned* a, const unsigned* b) {
    asm volatile(
        "mma.sync.aligned.m16n8k8.row.col.f32.tf32.tf32.f32 "
        "{%0,%1,%2,%3}, {%4,%5,%6,%7}, {%8,%9}, {%0,%1,%2,%3};"
        : "+f"(c[0]), "+f"(c[1]), "+f"(c[2]), "+f"(c[3])
        : "r"(a[0]), "r"(a[1]), "r"(a[2]), "r"(a[3]), "r"(b[0]), "r"(b[1]));
}

// ---------- scratch (device globals; allocation is forbidden) ----------
__device__ float g_X [16 * 2048 * 32];
__device__ float g_VA[16 * 2048 * 32];
__device__ float g_VB[16 * 2048 * 32];
__device__ float g_Upart[16 * 16 * 129 * 32];   // [b][chunk(16)][129][32] (row 128 = bias c)
__device__ float g_U[16 * 129 * 32];            // [b][129][32]
__device__ float g_partF[16 * 32 * 10];
__device__ unsigned g_tick;

// ---------- X = emb[data], with per-block int64/int32 detection ----------
__global__ __launch_bounds__(256) void k_gather(const int* __restrict__ d32,
                                                const float* __restrict__ emb) {
    __shared__ int s_is64;
    int tid = threadIdx.x;
    if (tid == 0) s_is64 = 1;
    __syncthreads();
    if (tid < 32) { if (d32[2 * tid + 1] != 0) s_is64 = 0; }
    __syncthreads();
    int t = blockIdx.x * 256 + tid;
    int row = t >> 3, q = t & 7;
    int idx = s_is64 ? d32[row * 2] : d32[row];
    float4 v = *reinterpret_cast<const float4*>(emb + (size_t)idx * 32 + q * 4);
    *reinterpret_cast<float4*>(g_X + (size_t)row * 32 + q * 4) = v;
}

// ---------- U partials via TF32 tensor cores (3xTF32 compensation) ----------
// (byte-identical to the 151.4us R9 kernel)
__global__ __launch_bounds__(256) void k_upart(const float* __restrict__ fw2,
                                               const float* __restrict__ fb2,
                                               int vin_sel, int layer) {
    __shared__ unsigned Bh[128 * 40];
    __shared__ unsigned Bl[128 * 40];
    __shared__ float   Sfb[128];
    int b = blockIdx.y, ch = blockIdx.x, tid = threadIdx.x;
    int m0 = ch * 128;
    const float* Vin = (vin_sel == 0) ? g_X : (vin_sel == 1 ? g_VA : g_VB);
    const float4* vg4 = reinterpret_cast<const float4*>(Vin + ((size_t)(b * 2048 + m0)) * 32);

#pragma unroll
    for (int it = 0; it < 4; ++it) {
        int t4 = tid + it * 256;
        int m = t4 >> 3, dq = (t4 & 7) * 4;
        float4 v = vg4[t4];
        unsigned* ph = Bh + m * 40 + dq;
        unsigned* pl = Bl + m * 40 + dq;
        unsigned h;
        h = f2tf32(v.x); ph[0] = h; pl[0] = f2tf32(v.x - __uint_as_float(h));
        h = f2tf32(v.y); ph[1] = h; pl[1] = f2tf32(v.y - __uint_as_float(h));
        h = f2tf32(v.z); ph[2] = h; pl[2] = f2tf32(v.z - __uint_as_float(h));
        h = f2tf32(v.w); ph[3] = h; pl[3] = f2tf32(v.w - __uint_as_float(h));
    }
    if (tid < 128) Sfb[tid] = fb2[(size_t)layer * 2048 + m0 + tid];
    __syncthreads();

    int w = tid >> 5, lane = tid & 31;
    int grp = lane >> 2, tig = lane & 3;
    const float* A0 = fw2 + ((size_t)(layer * 128 + w * 16 + grp)) * 2048 + m0;
    const float* A8 = A0 + (size_t)8 * 2048;

    float accM[4][4], accC[4][4];
#pragma unroll
    for (int nt = 0; nt < 4; ++nt)
#pragma unroll
        for (int i = 0; i < 4; ++i) { accM[nt][i] = 0.f; accC[nt][i] = 0.f; }

#pragma unroll 4
    for (int ks = 0; ks < 16; ++ks) {
        int c0 = ks * 8 + tig;
        float a0f = A0[c0], a1f = A8[c0], a2f = A0[c0 + 4], a3f = A8[c0 + 4];
        unsigned ah[4], al[4];
        ah[0] = f2tf32(a0f); al[0] = f2tf32(a0f - __uint_as_float(ah[0]));
        ah[1] = f2tf32(a1f); al[1] = f2tf32(a1f - __uint_as_float(ah[1]));
        ah[2] = f2tf32(a2f); al[2] = f2tf32(a2f - __uint_as_float(ah[2]));
        ah[3] = f2tf32(a3f); al[3] = f2tf32(a3f - __uint_as_float(ah[3]));
        const unsigned* rh0 = Bh + (ks * 8 + tig) * 40 + grp;
        const unsigned* rh4 = rh0 + 4 * 40;
        const unsigned* rl0 = Bl + (ks * 8 + tig) * 40 + grp;
        const unsigned* rl4 = rl0 + 4 * 40;
#pragma unroll
        for (int nt = 0; nt < 4; ++nt) {
            unsigned bh[2] = { rh0[nt * 8], rh4[nt * 8] };
            unsigned bl[2] = { rl0[nt * 8], rl4[nt * 8] };
            mma_tf32(accM[nt], ah, bh);
            mma_tf32(accC[nt], al, bh);
            mma_tf32(accC[nt], ah, bl);
        }
    }

    float* up = g_Upart + (((size_t)(b * 16 + ch)) * 129 + w * 16) * 32;
#pragma unroll
    for (int nt = 0; nt < 4; ++nt) {
        int d = nt * 8 + tig * 2;
        float2 r0 = make_float2(accM[nt][0] + accC[nt][0], accM[nt][1] + accC[nt][1]);
        float2 r1 = make_float2(accM[nt][2] + accC[nt][2], accM[nt][3] + accC[nt][3]);
        *reinterpret_cast<float2*>(up + grp * 32 + d) = r0;
        *reinterpret_cast<float2*>(up + (grp + 8) * 32 + d) = r1;
    }

    if (w == 0) {
        float acc = 0.f;
#pragma unroll 8
        for (int m = 0; m < 128; ++m)
            acc += Sfb[m] * (__uint_as_float(Bh[m * 40 + lane]) +
                             __uint_as_float(Bl[m * 40 + lane]));
        g_Upart[(((size_t)(b * 16 + ch)) * 129 + 128) * 32 + lane] = acc;
    }
}

// ---------- reduce split-K partials ----------
__global__ __launch_bounds__(256) void k_ured() {
    int idx = blockIdx.x * 256 + threadIdx.x;
    if (idx >= 16 * 1032) return;
    int b = idx / 1032, r4 = idx - b * 1032;
    const float4* base = reinterpret_cast<const float4*>(g_Upart) + (size_t)b * 16 * 1032 + r4;
    float4 s = make_float4(0.f, 0.f, 0.f, 0.f);
#pragma unroll
    for (int c = 0; c < 16; ++c) {
        float4 v = base[(size_t)c * 1032];
        s.x += v.x; s.y += v.y; s.z += v.z; s.w += v.w;
    }
    reinterpret_cast<float4*>(g_U)[(size_t)b * 1032 + r4] = s;
}

// ---------- fused tensor-core vupd: H = gelu(X@fw1+fb1); V' = H@U + c ----------
// 32 rows/block, 128 threads (4 warps), grid (64,16). Both GEMMs via 3xTF32 mma.
// dyn smem (u32): Uh[128*36] | Ul[128*36] | Hh[32*132] | Hl[32*132] | crow[32] | fb1s[128]
static const int VUPD_U32 = 128 * 36 * 2 + 32 * 132 * 2 + 32 + 128;   // 17824 u32 = 71296 B
__global__ __launch_bounds__(128) void k_vupd(const float* __restrict__ fw1,
                                              const float* __restrict__ fb1,
                                              int vout_sel, int layer) {
    extern __shared__ __align__(16) unsigned smu[];
    unsigned* Uh = smu;
    unsigned* Ul = Uh + 128 * 36;
    unsigned* Hh = Ul + 128 * 36;
    unsigned* Hl = Hh + 32 * 132;
    float* crow = reinterpret_cast<float*>(Hl + 32 * 132);
    float* fb1s = crow + 32;
    int b = blockIdx.y, n0 = blockIdx.x * 32, tid = threadIdx.x;

    // stage U (rows 0..127) hi/lo; crow = row 128; fb1s
    const float4* Ug4 = reinterpret_cast<const float4*>(g_U + (size_t)b * 4128);
#pragma unroll
    for (int it = 0; it < 8; ++it) {
        int t4 = tid + it * 128;                 // 1024 float4 = 128j x 8
        int j = t4 >> 3, dq = (t4 & 7) * 4;
        float4 v = Ug4[t4];
        unsigned* ph = Uh + j * 36 + dq;
        unsigned* pl = Ul + j * 36 + dq;
        unsigned h;
        h = f2tf32(v.x); ph[0] = h; pl[0] = f2tf32(v.x - __uint_as_float(h));
        h = f2tf32(v.y); ph[1] = h; pl[1] = f2tf32(v.y - __uint_as_float(h));
        h = f2tf32(v.z); ph[2] = h; pl[2] = f2tf32(v.z - __uint_as_float(h));
        h = f2tf32(v.w); ph[3] = h; pl[3] = f2tf32(v.w - __uint_as_float(h));
    }
    if (tid < 32) crow[tid] = g_U[(size_t)b * 4128 + 4096 + tid];
    fb1s[tid] = fb1[layer * 128 + tid];
    __syncthreads();

    int w = tid >> 5, lane = tid & 31;
    int grp = lane >> 2, tig = lane & 3;
    int mtb = (w & 1) * 16;                      // warp's 16-row m-tile base
    int ntb = (w >> 1) * 8;                      // GEMM1: 8 n-tiles (j)

    // ---- GEMM1: C1[32r x 128j] = X[32x32] @ fw1[32x128]  (A,B direct from L2) ----
    float c1M[8][4], c1C[8][4];
#pragma unroll
    for (int nt = 0; nt < 8; ++nt)
#pragma unroll
        for (int i = 0; i < 4; ++i) { c1M[nt][i] = 0.f; c1C[nt][i] = 0.f; }

    const float* X0 = g_X + ((size_t)(b * 2048 + n0 + mtb + grp)) * 32;
    const float* X8 = X0 + 8 * 32;
    const float* W = fw1 + (size_t)layer * 4096;
#pragma unroll
    for (int ks = 0; ks < 4; ++ks) {
        int k0 = 8 * ks + tig;
        float x0 = X0[k0], x1 = X8[k0], x2 = X0[k0 + 4], x3 = X8[k0 + 4];
        unsigned ah[4], al[4];
        ah[0] = f2tf32(x0); al[0] = f2tf32(x0 - __uint_as_float(ah[0]));
        ah[1] = f2tf32(x1); al[1] = f2tf32(x1 - __uint_as_float(ah[1]));
        ah[2] = f2tf32(x2); al[2] = f2tf32(x2 - __uint_as_float(ah[2]));
        ah[3] = f2tf32(x3); al[3] = f2tf32(x3 - __uint_as_float(ah[3]));
        const float* Wr0 = W + (size_t)k0 * 128;
        const float* Wr4 = W + (size_t)(k0 + 4) * 128;
#pragma unroll
        for (int nt = 0; nt < 8; ++nt) {
            int j = (ntb + nt) * 8 + grp;
            float b0 = Wr0[j], b1 = Wr4[j];
            unsigned bh[2], bl[2];
            bh[0] = f2tf32(b0); bl[0] = f2tf32(b0 - __uint_as_float(bh[0]));
            bh[1] = f2tf32(b1); bl[1] = f2tf32(b1 - __uint_as_float(bh[1]));
            mma_tf32(c1M[nt], ah, bh);
            mma_tf32(c1C[nt], al, bh);
            mma_tf32(c1C[nt], ah, bl);
        }
    }

    // ---- bias + exact GELU in-register, write H hi/lo to smem ----
#pragma unroll
    for (int nt = 0; nt < 8; ++nt) {
        int j0 = (ntb + nt) * 8 + tig * 2;
        float bj0 = fb1s[j0], bj1 = fb1s[j0 + 1];
#pragma unroll
        for (int hf = 0; hf < 2; ++hf) {
            int r = mtb + grp + hf * 8;
            float v0 = c1M[nt][hf * 2] + c1C[nt][hf * 2] + bj0;
            float v1 = c1M[nt][hf * 2 + 1] + c1C[nt][hf * 2 + 1] + bj1;
            float h0 = 0.5f * v0 * (1.0f + erff(v0 * 0.70710678118654752f));
            float h1 = 0.5f * v1 * (1.0f + erff(v1 * 0.70710678118654752f));
            unsigned hh0 = f2tf32(h0), hh1 = f2tf32(h1);
            unsigned lo0 = f2tf32(h0 - __uint_as_float(hh0));
            unsigned lo1 = f2tf32(h1 - __uint_as_float(hh1));
            *reinterpret_cast<uint2*>(Hh + r * 132 + j0) = make_uint2(hh0, hh1);
            *reinterpret_cast<uint2*>(Hl + r * 132 + j0) = make_uint2(lo0, lo1);
        }
    }
    __syncthreads();

    // ---- GEMM2: V'[32r x 32d] = H[32x128] @ U[128x32] + crow ----
    int ntb2 = (w >> 1) * 2;                     // 2 n-tiles (d) per warp
    float c2M[2][4], c2C[2][4];
#pragma unroll
    for (int nt = 0; nt < 2; ++nt)
#pragma unroll
        for (int i = 0; i < 4; ++i) { c2M[nt][i] = 0.f; c2C[nt][i] = 0.f; }

    int ra = (mtb + grp) * 132;
    int rb = ra + 8 * 132;
#pragma unroll 4
    for (int ks = 0; ks < 16; ++ks) {
        int k0 = 8 * ks + tig;
        unsigned ah[4] = { Hh[ra + k0], Hh[rb + k0], Hh[ra + k0 + 4], Hh[rb + k0 + 4] };
        unsigned al[4] = { Hl[ra + k0], Hl[rb + k0], Hl[ra + k0 + 4], Hl[rb + k0 + 4] };
#pragma unroll
        for (int nt = 0; nt < 2; ++nt) {
            int n = (ntb2 + nt) * 8 + grp;
            unsigned bh[2] = { Uh[k0 * 36 + n], Uh[(k0 + 4) * 36 + n] };
            unsigned bl[2] = { Ul[k0 * 36 + n], Ul[(k0 + 4) * 36 + n] };
            mma_tf32(c2M[nt], ah, bh);
            mma_tf32(c2C[nt], al, bh);
            mma_tf32(c2C[nt], ah, bl);
        }
    }

    float* Vout = (vout_sel == 1) ? g_VA : g_VB;
#pragma unroll
    for (int nt = 0; nt < 2; ++nt) {
        int d0 = (ntb2 + nt) * 8 + tig * 2;
        float cc0 = crow[d0], cc1 = crow[d0 + 1];
#pragma unroll
        for (int hf = 0; hf < 2; ++hf) {
            int r = n0 + mtb + grp + hf * 8;
            float2 o = make_float2(c2M[nt][hf * 2] + c2C[nt][hf * 2] + cc0,
                                   c2M[nt][hf * 2 + 1] + c2C[nt][hf * 2 + 1] + cc1);
            *reinterpret_cast<float2*>(Vout + ((size_t)(b * 2048 + r)) * 32 + d0) = o;
        }
    }
}

// ---------- final projection, fused partial + completion (ticket) ----------
__global__ __launch_bounds__(256) void k_fproj(const float* __restrict__ Wf,
                                               const float* __restrict__ bf,
                                               float* __restrict__ out) {
    __shared__ float wsum[8][10];
    __shared__ int s_last;
    int b = blockIdx.y, ch = blockIdx.x, tid = threadIdx.x;
    int lane = tid & 31, w = tid >> 5;
    float acc[10];
#pragma unroll
    for (int c = 0; c < 10; ++c) acc[c] = 0.f;
    const float* Vb = g_VB + (size_t)b * 65536 + ch * 2048;
#pragma unroll
    for (int q = 0; q < 8; ++q) {
        int k = q * 256 + tid;
        float v = Vb[k];
        const float* wr = Wf + (size_t)(ch * 2048 + k) * 10;
#pragma unroll
        for (int c = 0; c < 10; ++c) acc[c] += v * wr[c];
    }
#pragma unroll
    for (int c = 0; c < 10; ++c) {
#pragma unroll
        for (int s = 16; s > 0; s >>= 1) acc[c] += __shfl_down_sync(0xffffffffu, acc[c], s);
        if (lane == 0) wsum[w][c] = acc[c];
    }
    __syncthreads();
    if (tid < 10) {
        float s = 0.f;
#pragma unroll
        for (int ww = 0; ww < 8; ++ww) s += wsum[ww][tid];
        g_partF[((size_t)(b * 32 + ch)) * 10 + tid] = s;
    }
    __threadfence();
    __syncthreads();
    if (tid == 0) {
        unsigned prev = atomicAdd(&g_tick, 1u);
        s_last = (prev == 511u) ? 1 : 0;
    }
    __syncthreads();
    if (s_last) {
        __threadfence();
        if (tid < 160) {
            int bb = tid / 10, c = tid % 10;
            float s = bf[c];
#pragma unroll
            for (int cc = 0; cc < 32; ++cc) s += g_partF[((size_t)(bb * 32 + cc)) * 10 + c];
            out[tid] = s;
        }
        if (tid == 0) g_tick = 0u;
    }
}

extern "C" void kernel_launch(void* const* d_in, const int* in_sizes, int n_in,
                              void* d_out, int out_size) {
    const int*   data = (const int*)  d_in[0];
    const float* emb  = (const float*)d_in[1];
    const float* fw1  = (const float*)d_in[2];
    const float* fb1  = (const float*)d_in[3];
    const float* fw2  = (const float*)d_in[4];
    const float* fb2  = (const float*)d_in[5];
    const float* Wf   = (const float*)d_in[6];
    const float* bf   = (const float*)d_in[7];
    float* out = (float*)d_out;

    const int VUPD_SMEM = VUPD_U32 * 4;          // 71296 B -> 3 blocks/SM
    cudaFuncSetAttribute(k_vupd, cudaFuncAttributeMaxDynamicSharedMemorySize, VUPD_SMEM);

    k_gather<<<1024, 256>>>(data, emb);

    // layers i = 3,2,1,0 ; V ping-pong: X -> VA -> VB -> VA -> VB
    int vin = 0;
    for (int it = 0; it < 4; ++it) {
        int layer = 3 - it;
        int vout = (vin == 1) ? 2 : 1;
        k_upart<<<dim3(16, 16), 256>>>(fw2, fb2, vin, layer);
        k_ured<<<65, 256>>>();
        k_vupd<<<dim3(64, 16), 128, VUPD_SMEM>>>(fw1, fb1, vout, layer);
        vin = vout;
    }

    k_fproj<<<dim3(32, 16), 256>>>(Wf, bf, out);
}